// round 17
// baseline (speedup 1.0000x reference)
#include <cuda_runtime.h>
#include <cuda_bf16.h>

// Problem constants
#define TT   4096
#define HH   16
#define DKK  128
#define QKVC 6144
#define NELEM (TT * HH * DKK)   // 8388608

// Scratch (static __device__ globals — no runtime allocation)
// g_P packed per (t,h): [slot0(128) | a(128) | k(128) | q(128)]
// slot0 holds ka after prep; pass2 overwrites it in place with
// w_t = ka_t ∘ a_{t-1} ∘ a_{t-2} (only warp (t,h) ever touches slot0 of (t,h)).
__device__ __align__(16) float g_P [TT * HH * 512];
__device__ __align__(16) float g_BV[NELEM];        // b * (conv+silu v)
__device__ __align__(16) float g_S4[TT * HH * 4];  // {b, R, Q, 0} per (t,h)
__device__ float g_B[TT * HH];                     // sigmoid(beta)

typedef unsigned long long ull;

// --------------------------------------------------------------------------
// f32x2 packed-math helpers (FFMA2 path; ptxas only emits via PTX f32x2)
// --------------------------------------------------------------------------
__device__ __forceinline__ ull ffma2(ull a, ull b, ull c) {
    ull d;
    asm("fma.rn.f32x2 %0, %1, %2, %3;" : "=l"(d) : "l"(a), "l"(b), "l"(c));
    return d;
}
__device__ __forceinline__ ull fmul2(ull a, ull b) {
    ull d;
    asm("mul.rn.f32x2 %0, %1, %2;" : "=l"(d) : "l"(a), "l"(b));
    return d;
}
__device__ __forceinline__ float hsum2(ull a) {
    float lo, hi;
    asm("mov.b64 {%0, %1}, %2;" : "=f"(lo), "=f"(hi) : "l"(a));
    return lo + hi;
}
__device__ __forceinline__ ull pack2(float x) {
    ull d;
    asm("mov.b64 %0, {%1, %1};" : "=l"(d) : "f"(x));
    return d;
}

// cp.async helper
__device__ __forceinline__ void cp16(float* dst, const float* src) {
    unsigned d = (unsigned)__cvta_generic_to_shared(dst);
    asm volatile("cp.async.cg.shared.global [%0], [%1], 16;"
                 :: "r"(d), "l"(src) : "memory");
}

// --------------------------------------------------------------------------
// Kernel 1: conv1d(K=4, depthwise, causal) + SiLU + l2norm + gate precompute.
// One warp per (t-pair, h) — outputs t0 and t0+1. Shares 3 of 5 qkv rows and
// all 12 weight vectors between the two outputs. (identical to R16)
// --------------------------------------------------------------------------
__global__ void __launch_bounds__(256)
prep_kernel(const float* __restrict__ qkv,
            const float* __restrict__ fg,
            const float* __restrict__ beta,
            const float* __restrict__ w,
            const float* __restrict__ A_log,
            const float* __restrict__ dt_bias) {
    int gw   = (blockIdx.x * blockDim.x + threadIdx.x) >> 5;
    int lane = threadIdx.x & 31;
    if (gw >= TT * HH / 2) return;
    int t0 = (gw >> 4) << 1;     // even
    int h  = gw & 15;
    int d  = lane * 4;
    int cbase = h * DKK + d;

    // outputs: [step][seg*4+j]  (q: 0-3, k: 4-7, v: 8-11)
    float oy[2][12];
    const float4 z4 = make_float4(0.f, 0.f, 0.f, 0.f);

#pragma unroll
    for (int seg = 0; seg < 3; seg++) {
        const int c = cbase + seg * 2048;
        float wz[4][4];
#pragma unroll
        for (int j = 0; j < 4; j++) {
            float4 wv = *(const float4*)(w + (size_t)(c + j) * 4);
            wz[j][0] = wv.x; wz[j][1] = wv.y; wz[j][2] = wv.z; wz[j][3] = wv.w;
        }
        float4 xr[5];
#pragma unroll
        for (int i = 0; i < 5; i++) {
            int r = t0 - 3 + i;
            xr[i] = (r >= 0) ? *(const float4*)(qkv + (size_t)r * QKVC + c)
                             : z4;
        }
#pragma unroll
        for (int s = 0; s < 2; s++) {
            float acc[4] = {0.f, 0.f, 0.f, 0.f};
#pragma unroll
            for (int tau = 0; tau < 4; tau++) {
                const float4 xv = xr[s + tau];
                acc[0] = fmaf(xv.x, wz[0][tau], acc[0]);
                acc[1] = fmaf(xv.y, wz[1][tau], acc[1]);
                acc[2] = fmaf(xv.z, wz[2][tau], acc[2]);
                acc[3] = fmaf(xv.w, wz[3][tau], acc[3]);
            }
#pragma unroll
            for (int j = 0; j < 4; j++)
                oy[s][seg * 4 + j] = acc[j] / (1.f + expf(-acc[j]));  // SiLU
        }
    }

    float  ea  = expf(A_log[h]);
    float4 dbv = *(const float4*)(dt_bias + h * DKK + d);

#pragma unroll
    for (int s = 0; s < 2; s++) {
        const int t = t0 + s;
        const float* qy = &oy[s][0];
        const float* ky = &oy[s][4];
        const float* vy = &oy[s][8];

        float sq = 0.f, sk = 0.f;
#pragma unroll
        for (int j = 0; j < 4; j++) {
            sq = fmaf(qy[j], qy[j], sq);
            sk = fmaf(ky[j], ky[j], sk);
        }
#pragma unroll
        for (int m = 16; m > 0; m >>= 1) {
            sq += __shfl_xor_sync(0xffffffffu, sq, m);
            sk += __shfl_xor_sync(0xffffffffu, sk, m);
        }
        float se_q = sq + 1e-6f, se_k = sk + 1e-6f;
        float rq = rsqrtf(se_q); rq = rq * (1.5f - 0.5f * se_q * rq * rq);
        float rk = rsqrtf(se_k); rk = rk * (1.5f - 0.5f * se_k * rk * rk);
        rq *= 0.08838834764831845f;   // DK^-0.5

        float4 fgv = *(const float4*)(fg + (size_t)t * (HH * DKK) + h * DKK + d);
        float zf[4] = {fgv.x + dbv.x, fgv.y + dbv.y, fgv.z + dbv.z, fgv.w + dbv.w};
        float bb = 1.f / (1.f + expf(-beta[t * HH + h]));

        float qn[4], kn[4], av[4], kav[4];
#pragma unroll
        for (int j = 0; j < 4; j++) {
            float z  = zf[j];
            float sp = (z > 20.f) ? z : log1pf(expf(z));   // softplus
            av[j]  = expf(-ea * sp);                       // a = exp(g)
            qn[j]  = qy[j] * rq;
            kn[j]  = ky[j] * rk;
            kav[j] = kn[j] * av[j];
        }

        size_t pb = ((size_t)t * HH + h) * 512 + d;
        *(float4*)(g_P + pb      ) = make_float4(kav[0], kav[1], kav[2], kav[3]);
        *(float4*)(g_P + pb + 128) = make_float4(av[0],  av[1],  av[2],  av[3]);
        *(float4*)(g_P + pb + 256) = make_float4(kn[0],  kn[1],  kn[2],  kn[3]);
        *(float4*)(g_P + pb + 384) = make_float4(qn[0],  qn[1],  qn[2],  qn[3]);
        *(float4*)(g_BV + ((size_t)t * HH + h) * DKK + d) =
            make_float4(vy[0] * bb, vy[1] * bb, vy[2] * bb, vy[3] * bb);
        if (lane == 0)
            g_B[t * HH + h] = bb;
    }
}

// --------------------------------------------------------------------------
// Kernel 1b: lookahead precompute, 2 timesteps per warp (t0 even, t0+1).
// Shares neighbor a/k loads (8 float4 loads per 2 steps vs 10) and reduces
// the 4 scalars (rp0,qp0,rp1,qp1) with one 6-SHFL split-butterfly.
//   w_t = ka_t ∘ a_{t-1} ∘ a_{t-2}      (overwrite slot0 in place)
//   R_t = (ka_t ∘ a_{t-1}) · k_{t-2},  Q_t = ka_t · k_{t-1}
// Negative t indices: a := 1, k := 0.
// --------------------------------------------------------------------------
__global__ void __launch_bounds__(256)
pass2_kernel() {
    int gw   = (blockIdx.x * blockDim.x + threadIdx.x) >> 5;
    int lane = threadIdx.x & 31;
    if (gw >= TT * HH / 2) return;
    int t0 = (gw >> 4) << 1;     // even
    int h  = gw & 15;
    int d  = lane * 4;

    const size_t ts  = (size_t)HH * 512;
    size_t bt0 = ((size_t)t0 * HH + h) * 512;
    size_t bt1 = bt0 + ts;

    float4 ka0 = *(const float4*)(g_P + bt0 +       d);
    float4 ka1 = *(const float4*)(g_P + bt1 +       d);
    float4 a0  = *(const float4*)(g_P + bt0 + 128 + d);   // a_{t0}
    float4 k0  = *(const float4*)(g_P + bt0 + 256 + d);   // k_{t0}
    float4 am1 = make_float4(1.f, 1.f, 1.f, 1.f);
    float4 am2 = make_float4(1.f, 1.f, 1.f, 1.f);
    float4 km1 = make_float4(0.f, 0.f, 0.f, 0.f);
    float4 km2 = make_float4(0.f, 0.f, 0.f, 0.f);
    if (t0 > 0) {   // t0 even: either 0 or >= 2
        am1 = *(const float4*)(g_P + bt0 -     ts + 128 + d);
        km1 = *(const float4*)(g_P + bt0 -     ts + 256 + d);
        am2 = *(const float4*)(g_P + bt0 - 2 * ts + 128 + d);
        km2 = *(const float4*)(g_P + bt0 - 2 * ts + 256 + d);
    }

    // t0 terms
    float4 u0 = make_float4(ka0.x * am1.x, ka0.y * am1.y,
                            ka0.z * am1.z, ka0.w * am1.w);
    float4 w0 = make_float4(u0.x * am2.x, u0.y * am2.y,
                            u0.z * am2.z, u0.w * am2.w);
    float rp0 = fmaf(u0.x, km2.x, u0.y * km2.y) + fmaf(u0.z, km2.z, u0.w * km2.w);
    float qp0 = fmaf(ka0.x, km1.x, ka0.y * km1.y) + fmaf(ka0.z, km1.z, ka0.w * km1.w);
    // t0+1 terms
    float4 u1 = make_float4(ka1.x * a0.x, ka1.y * a0.y,
                            ka1.z * a0.z, ka1.w * a0.w);
    float4 w1 = make_float4(u1.x * am1.x, u1.y * am1.y,
                            u1.z * am1.z, u1.w * am1.w);
    float rp1 = fmaf(u1.x, km1.x, u1.y * km1.y) + fmaf(u1.z, km1.z, u1.w * km1.w);
    float qp1 = fmaf(ka1.x, k0.x, ka1.y * k0.y) + fmaf(ka1.z, k0.z, ka1.w * k0.w);

    // 4-value split-butterfly (6 SHFL):
    const bool lo16 = (lane < 16);
    const bool lo8  = ((lane & 8) == 0);
    float e1 = lo16 ? rp1 : rp0;
    float r1 = __shfl_xor_sync(0xffffffffu, e1, 16);
    float u  = (lo16 ? rp0 : rp1) + r1;
    float e2 = lo16 ? qp1 : qp0;
    float r2 = __shfl_xor_sync(0xffffffffu, e2, 16);
    float u2 = (lo16 ? qp0 : qp1) + r2;
    float e3 = lo8 ? u2 : u;
    float r3 = __shfl_xor_sync(0xffffffffu, e3, 8);
    float v  = (lo8 ? u : u2) + r3;
    v += __shfl_xor_sync(0xffffffffu, v, 4);
    v += __shfl_xor_sync(0xffffffffu, v, 2);
    v += __shfl_xor_sync(0xffffffffu, v, 1);
    // v: lanes 0-7 = rp0, 8-15 = qp0, 16-23 = rp1, 24-31 = qp1

    float qpv = __shfl_sync(0xffffffffu, v, (lane & 16) | 8);

    *(float4*)(g_P + bt0 + d) = w0;           // slot0 := w (warp-private)
    *(float4*)(g_P + bt1 + d) = w1;
    if ((lane & 15) == 0) {
        int tt = t0 + (lane >> 4);
        *(float4*)(g_S4 + ((size_t)tt * HH + h) * 4) =
            make_float4(g_B[tt * HH + h], v, qpv, 0.f);
    }
}

// --------------------------------------------------------------------------
// Kernel 2: gated delta-rule recurrence with 3-step lookahead.
// CTA = 256 threads (8 warps) = 16 v-columns; one warp = 2 v-columns.
// Lane owns k-quad 4*lane..4*lane+3 (distinct-per-lane LDS.128).
// Scalar HALF-LANE chain (lanes 0-15 col A, 16-31 col B).
//
// R17 change vs R15: reductions batched over step-PAIRS — the 8 partials
// (o,p x 2 cols x 2 steps) reduce in one 9-SHFL split-butterfly; P routing
// = 2 idx-shfl per pair; output = 1 predicated per-lane-addressed STG from
// lanes {0,4,8,12}. Chain and S-update unchanged.
// --------------------------------------------------------------------------
#define STGF 544   // floats per stage: 512 packed + 16 bv + 4 scalars + pad
#define NST  16    // 4 groups x 4 steps in-flight ring

__global__ void __launch_bounds__(256, 1)
recur_kernel(float* __restrict__ out) {
    __shared__ __align__(16) float sm[NST * STGF];

    const int tid  = threadIdx.x;
    const int warp = tid >> 5;
    const int lane = tid & 31;
    const int h    = blockIdx.x >> 3;
    const int vb   = (blockIdx.x & 7) * 16;       // CTA's 16-column slab
    float* outp = out + h * DKK + vb + warp * 2;

    auto issue = [&](int g) {
#pragma unroll
        for (int s = 0; s < 4; s++) {
            int tu = 4 * g + s;
            float* sp = sm + (tu & 15) * STGF;
            int t = (tu > TT - 1) ? (TT - 1) : tu;
            const float* gp = g_P + ((size_t)t * HH + h) * 512;
            if (tid < 128) cp16(sp + tid * 4, gp + tid * 4);
            if (tid >= 128 && tid < 132)
                cp16(sp + 512 + (tid - 128) * 4,
                     g_BV + ((size_t)t * HH + h) * DKK + vb + (tid - 128) * 4);
            if (tid == 132)
                cp16(sp + 528, g_S4 + ((size_t)t * HH + h) * 4);
        }
        asm volatile("cp.async.commit_group;" ::: "memory");
    };

    issue(0); issue(1); issue(2);

    ull SA0 = 0, SA1 = 0, SB0 = 0, SB1 = 0;
    float Pq[4] = {0.f, 0.f, 0.f, 0.f};   // per-half reduced P, steps t..t+3
    float d1 = 0.f, d2 = 0.f;             // per-half delta_{t-1}, delta_{t-2}
    const bool lo16 = (lane < 16);
    const bool lo8  = ((lane & 8) == 0);
    const bool lo4  = ((lane & 4) == 0);
    // per-half bv smem offset: col A for lanes 0-15, col B for lanes 16-31
    const int  bvix = 512 + warp * 2 + (lane >> 4);
    // P idx-shfl sources (own half): p of step0 @ {16,24}, step1 @ {20,28}
    const int  psrc0 = lo16 ? 16 : 24;
    const int  psrc1 = lo16 ? 20 : 28;
    // predicated store: lanes 0,4,8,12 -> (col = bit3, toff = bit2)
    float* sout = outp + ((lane >> 3) & 1);
    const int  toff = (lane >> 2) & 1;
    const bool do_store = ((lane & 3) == 0) && lo16;

    for (int g = 0; g < TT / 4; g++) {
        // groups g and g+1 complete (w of t+3 lives in group g+1)
        asm volatile("cp.async.wait_group 1;" ::: "memory");
        __syncthreads();
#pragma unroll
        for (int sp2 = 0; sp2 < 2; sp2++) {
            const int t = 4 * g + 2 * sp2;
            float oa[2], ob[2], pa[2], pb[2];
#pragma unroll
            for (int ss = 0; ss < 2; ss++) {
                const int tt = t + ss;
                const float* spb = sm + (tt & 15) * STGF;
                const float* spn = sm + ((tt + 3) & 15) * STGF;  // w_{tt+3}
                const int lo = lane * 4;

                // distinct-per-lane array loads (one LDS.128 per array)
                ulonglong2 A = *(const ulonglong2*)(spb + 128 + lo);
                ulonglong2 K = *(const ulonglong2*)(spb + 256 + lo);
                ulonglong2 Q = *(const ulonglong2*)(spb + 384 + lo);
                ulonglong2 W = *(const ulonglong2*)(spn + lo);

                float4 s4 = *(const float4*)(spb + 528);    // {b, R, Q, -}
                float  bv = spb[bvix];                      // per-half bv

                // ---- critical chain: 3 dependent scalar FFMAs ----
                float r  = fmaf(d2, s4.y, Pq[tt & 3]);
                r        = fmaf(d1, s4.z, r);
                float dt = fmaf(-s4.x, r, bv);
                d2 = d1; d1 = dt;

                // exchange dt across halves for the S update (off-chain)
                float dto = __shfl_xor_sync(0xffffffffu, dt, 16);
                ull DA = pack2(lo16 ? dt  : dto);
                ull DB = pack2(lo16 ? dto : dt);

                // ---- off-chain: S update + o-dot + P-dot partials ----
                SA0 = ffma2(A.x, SA0, fmul2(K.x, DA));
                SA1 = ffma2(A.y, SA1, fmul2(K.y, DA));
                SB0 = ffma2(A.x, SB0, fmul2(K.x, DB));
                SB1 = ffma2(A.y, SB1, fmul2(K.y, DB));

                oa[ss] = hsum2(ffma2(Q.x, SA0, fmul2(Q.y, SA1)));
                ob[ss] = hsum2(ffma2(Q.x, SB0, fmul2(Q.y, SB1)));
                pa[ss] = hsum2(ffma2(W.x, SA0, fmul2(W.y, SA1)));
                pb[ss] = hsum2(ffma2(W.x, SB0, fmul2(W.y, SB1)));
            }

            // ---- 8-value split-butterfly over the pair: 9 SHFL ----
            // level 16: 4 pairs (o,p) per column per step
            float t1 = lo16 ? pa[0] : oa[0];
            float u1 = (lo16 ? oa[0] : pa[0]) + __shfl_xor_sync(0xffffffffu, t1, 16);
            float t2 = lo16 ? pb[0] : ob[0];
            float u2 = (lo16 ? ob[0] : pb[0]) + __shfl_xor_sync(0xffffffffu, t2, 16);
            float t3 = lo16 ? pa[1] : oa[1];
            float u3 = (lo16 ? oa[1] : pa[1]) + __shfl_xor_sync(0xffffffffu, t3, 16);
            float t4 = lo16 ? pb[1] : ob[1];
            float u4 = (lo16 ? ob[1] : pb[1]) + __shfl_xor_sync(0xffffffffu, t4, 16);
            // level 8: (u1,u2) and (u3,u4)
            float t5 = lo8 ? u2 : u1;
            float v1 = (lo8 ? u1 : u2) + __shfl_xor_sync(0xffffffffu, t5, 8);
            float t6 = lo8 ? u4 : u3;
            float v2 = (lo8 ? u3 : u4) + __shfl_xor_sync(0xffffffffu, t6, 8);
            // level 4: (v1,v2)
            float t7 = lo4 ? v2 : v1;
            float v  = (lo4 ? v1 : v2) + __shfl_xor_sync(0xffffffffu, t7, 4);
            // levels 2,1: plain
            v += __shfl_xor_sync(0xffffffffu, v, 2);
            v += __shfl_xor_sync(0xffffffffu, v, 1);
            // v by 4-lane group: 0:oa0 4:oa1 8:ob0 12:ob1 16:pa0 20:pa1 24:pb0 28:pb1

            // per-half P for steps t+3, t+4
            Pq[(t + 3) & 3] = __shfl_sync(0xffffffffu, v, psrc0);
            Pq[(t + 4) & 3] = __shfl_sync(0xffffffffu, v, psrc1);
            // single predicated store: lanes 0,4,8,12 (col x toff)
            if (do_store)
                sout[(size_t)(t + toff) * (HH * DKK)] = v;
        }
        issue(g + 3);
    }
}

// --------------------------------------------------------------------------
extern "C" void kernel_launch(void* const* d_in, const int* in_sizes, int n_in,
                              void* d_out, int out_size) {
    const float* mixed_qkv   = (const float*)d_in[0];
    const float* forget_gate = (const float*)d_in[1];
    const float* beta        = (const float*)d_in[2];
    const float* conv_w      = (const float*)d_in[3];
    const float* A_log       = (const float*)d_in[4];
    const float* dt_bias     = (const float*)d_in[5];
    float* out = (float*)d_out;

    // 32768 (t-pair, h) warps, 8 per 256-thread block
    prep_kernel<<<(TT * HH / 2) / 8, 256>>>(mixed_qkv, forget_gate, beta,
                                            conv_w, A_log, dt_bias);
    pass2_kernel<<<(TT * HH / 2) / 8, 256>>>();
    recur_kernel<<<128, 256>>>(out);
}